// round 17
// baseline (speedup 1.0000x reference)
#include <cuda_runtime.h>
#include <cuda_fp16.h>
#include <stdint.h>
#include <math.h>

#define Dm   2048
#define Sm   512
#define Hn   16
#define HKVn 4
#define DHn  128
#define Fn   2048
#define En   8
#define QKVP 3072

// ---------------- scratch (device globals) ----------------
__device__ float g_qkv[Sm*QKVP];
__device__ float g_scores[Hn*Sm*Sm];
__device__ float g_h[Sm*Dm];
__device__ float g_x2f[Sm*Dm];
__device__ float g_gu[Sm*4096];
__device__ float g_sgu[Sm*4096];
__device__ float g_routed[Sm*Dm];
__device__ float g_shared[Sm*Dm];
__device__ int   g_topidx[Sm];
__device__ float g_topscore[Sm];
__device__ int   g_cnt[En];
__device__ int   g_list[En*Sm];

// activation fp16 planes
__device__ __half x_h[Sm*Dm];
__device__ __half at_h[Sm*Dm];
__device__ __half x2_h[Sm*Dm];
__device__ __half ac_h[Sm*Dm];
__device__ __half sa_h[Sm*Dm];
__device__ __half q_h[Sm*Dm];
__device__ __half k_h[Sm*512];
__device__ __half v_h[Sm*512];
__device__ __half p_h[Hn*Sm*Sm];

// ---------------- helpers ----------------
__device__ __forceinline__ uint32_t smem_u32(const void* p) {
    uint32_t a;
    asm("{ .reg .u64 t; cvta.to.shared.u64 t, %1; cvt.u32.u64 %0, t; }" : "=r"(a) : "l"(p));
    return a;
}
__device__ __forceinline__ uint32_t pack_f16x2(float a, float b) {
    __half2 h = __floats2half2_rn(a, b);
    return *(uint32_t*)&h;
}
__device__ __forceinline__ void mma16816(float c[4], const uint32_t a[4], const uint32_t b[2]) {
    asm volatile(
        "mma.sync.aligned.m16n8k16.row.col.f32.f16.f16.f32 "
        "{%0,%1,%2,%3}, {%4,%5,%6,%7}, {%8,%9}, {%0,%1,%2,%3};"
        : "+f"(c[0]), "+f"(c[1]), "+f"(c[2]), "+f"(c[3])
        : "r"(a[0]), "r"(a[1]), "r"(a[2]), "r"(a[3]), "r"(b[0]), "r"(b[1]));
}
__device__ __forceinline__ void cpa16(uint32_t d, const void* s) {
    asm volatile("cp.async.cg.shared.global [%0], [%1], 16;" :: "r"(d), "l"(s));
}
#define CPA_COMMIT() asm volatile("cp.async.commit_group;" ::: "memory")
#define CPA_WAIT1()  asm volatile("cp.async.wait_group 1;" ::: "memory")
#define CPA_WAIT0()  asm volatile("cp.async.wait_group 0;" ::: "memory")
__device__ __forceinline__ void ldm_x4(uint32_t r[4], uint32_t a) {
    asm volatile("ldmatrix.sync.aligned.m8n8.x4.shared.b16 {%0,%1,%2,%3}, [%4];"
        : "=r"(r[0]), "=r"(r[1]), "=r"(r[2]), "=r"(r[3]) : "r"(a));
}
__device__ __forceinline__ void ldm_x4t(uint32_t r[4], uint32_t a) {
    asm volatile("ldmatrix.sync.aligned.m8n8.x4.trans.shared.b16 {%0,%1,%2,%3}, [%4];"
        : "=r"(r[0]), "=r"(r[1]), "=r"(r[2]), "=r"(r[3]) : "r"(a));
}

// =============== fp16 1-pass HMMA GEMM, 128x128 tile, K=2048, KST=64 ===============
// 256 threads, 8 warps in 4(M)x2(N), warp tile 32x64, 2 CTAs/SM.
// B: LDG fp32 -> regs (1-stage prefetch) -> convert -> STS fp16 (double buf)
// A: cp.async fp16 plane (triple buf). ONE barrier per 64-k stage (32 stages).
#define KST 64
#define A_PITCH 72
#define A_PLANE_B (128*A_PITCH*2)     // 18432
#define BB_PITCH 136
#define BB_PLANE_B (KST*BB_PITCH*2)   // 17408
#define OFF_BB (3*A_PLANE_B)          // 55296
#define TG_SMEM (OFF_BB + 2*BB_PLANE_B)  // 90112

__global__ void __launch_bounds__(256, 2) tgemm_kernel(
    const __half* __restrict__ aH,
    const float* __restrict__ B0, const float* __restrict__ B1, const float* __restrict__ B2,
    int ldb0, int ldb1, int ldb2, int ns1, int ns2,
    float* __restrict__ C, int ldc,
    const float* __restrict__ res, const float* __restrict__ rowscale, int mode,
    const __half* __restrict__ sAh,
    const float* __restrict__ sB0, const float* __restrict__ sB1,
    float* __restrict__ sC)
{
    extern __shared__ char smc[];
    __shared__ int   tok[128];
    __shared__ float scl[128];
    int row0 = blockIdx.y * 128;
    int n0   = blockIdx.x * 128;
    int tid  = threadIdx.x;

    int gather = mode;
    if (mode == 1 && blockIdx.z == En) {
        aH = sAh; B0 = sB0; B1 = sB1; C = sC;
        rowscale = nullptr;
        gather = 0;
    }

    const float* Bsel; int ldbs; int ncol;
    if (n0 < ns1)      { Bsel = B0; ldbs = ldb0; ncol = n0; }
    else if (n0 < ns2) { Bsel = B1; ldbs = ldb1; ncol = n0 - ns1; }
    else               { Bsel = B2; ldbs = ldb2; ncol = n0 - ns2; }

    if (gather) {
        int e = blockIdx.z;
        int count = g_cnt[e];
        if (row0 >= count) return;
        Bsel += (size_t)e * 2048 * ldbs;
        if (tid < 128) {
            int r = row0 + tid;
            int t = (r < count) ? g_list[e * Sm + r] : -1;
            tok[tid] = t;
            scl[tid] = (t >= 0 && rowscale) ? rowscale[t] : 1.0f;
        }
    } else {
        if (tid < 128) { tok[tid] = row0 + tid; scl[tid] = 1.0f; }
    }
    __syncthreads();

    uint32_t smbase = smem_u32(smc);
    int lane = tid & 31, wid = tid >> 5;
    int gr = lane >> 2, tg = lane & 3;
    int wm = wid >> 1, wn = wid & 1;   // 4 x 2 warps; warp tile 32x64

    float acc[2][8][4];
#pragma unroll
    for (int i = 0; i < 2; i++)
#pragma unroll
        for (int j = 0; j < 8; j++)
#pragma unroll
            for (int r = 0; r < 4; r++) acc[i][j][r] = 0.f;

    int bk[8], bc[8];
#pragma unroll
    for (int it = 0; it < 8; it++) {
        int chunk = it * 256 + tid;
        bk[it] = chunk >> 5;
        bc[it] = (chunk & 31) * 4;
    }

    auto copy_A = [&](int st) {
        uint32_t ab = smbase + (uint32_t)(st % 3) * A_PLANE_B;
        int k0 = st * KST;
#pragma unroll
        for (int it = 0; it < 4; it++) {
            int chunk = it * 256 + tid;
            int row = chunk >> 3, ch = chunk & 7;
            int t = tok[row];
            int grow = t < 0 ? 0 : t;
            cpa16(ab + (uint32_t)(row * A_PITCH + ch * 8) * 2,
                  aH + (size_t)grow * 2048 + k0 + ch * 8);
        }
        CPA_COMMIT();
    };

    float4 va[8];
    auto ldg_B = [&](int st) {
        int k0 = st * KST;
#pragma unroll
        for (int it = 0; it < 8; it++)
            va[it] = *(const float4*)(Bsel + (size_t)(k0 + bk[it]) * ldbs + ncol + bc[it]);
    };

    ldg_B(0);
    copy_A(0);

    int lr = lane & 15;
    int lc8 = (lane & 16) >> 1;

    for (int st = 0; st < 32; st++) {
        // convert B(st) from regs -> BB[st&1]
        {
            __half* bh = (__half*)(smc + OFF_BB + (st & 1) * BB_PLANE_B);
#pragma unroll
            for (int it = 0; it < 8; it++) {
                float4 v = va[it];
                uint32_t h01 = pack_f16x2(v.x, v.y);
                uint32_t h23 = pack_f16x2(v.z, v.w);
                int o = bk[it] * BB_PITCH + bc[it];
                *(uint2*)(bh + o) = make_uint2(h01, h23);
            }
        }
        if (st < 31) {
            ldg_B(st + 1);
            copy_A(st + 1);
            CPA_WAIT1();
        } else {
            CPA_WAIT0();
        }
        __syncthreads();

        // ---- MMA: 4 k16 steps, warp tile 32x64 ----
        uint32_t AHb = smbase + (uint32_t)(st % 3) * A_PLANE_B;
        uint32_t BHb = smbase + OFF_BB + (uint32_t)(st & 1) * BB_PLANE_B;
#pragma unroll
        for (int ks = 0; ks < 4; ks++) {
            uint32_t fAH[2][4], fBH[8][2];
#pragma unroll
            for (int mt = 0; mt < 2; mt++) {
                uint32_t ao = (uint32_t)((wm * 32 + mt * 16 + lr) * A_PITCH + ks * 16 + lc8) * 2;
                ldm_x4(fAH[mt], AHb + ao);
            }
#pragma unroll
            for (int half = 0; half < 4; half++) {
                int brow = ks * 16 + lr;
                int bcol = wn * 64 + half * 16 + lc8;
                uint32_t bo = (uint32_t)(brow * BB_PITCH + bcol) * 2;
                uint32_t rH[4];
                ldm_x4t(rH, BHb + bo);
                fBH[half*2][0] = rH[0]; fBH[half*2][1] = rH[1];
                fBH[half*2+1][0] = rH[2]; fBH[half*2+1][1] = rH[3];
            }
#pragma unroll
            for (int mt = 0; mt < 2; mt++)
#pragma unroll
                for (int nt = 0; nt < 8; nt++)
                    mma16816(acc[mt][nt], fAH[mt], fBH[nt]);
        }
    }

    // ---- epilogue ----
#pragma unroll
    for (int mt = 0; mt < 2; mt++) {
        int r1 = wm * 32 + mt * 16 + gr;
        int r2 = r1 + 8;
        int t1 = tok[r1], t2 = tok[r2];
        float s1 = scl[r1], s2 = scl[r2];
#pragma unroll
        for (int nt = 0; nt < 8; nt++) {
            int col = n0 + wn * 64 + nt * 8 + tg * 2;
            if (t1 >= 0) {
                float2 o = make_float2(acc[mt][nt][0] * s1, acc[mt][nt][1] * s1);
                if (res) {
                    float2 rv = *(const float2*)(res + (size_t)t1 * ldc + col);
                    o.x += rv.x; o.y += rv.y;
                }
                *(float2*)(C + (size_t)t1 * ldc + col) = o;
            }
            if (t2 >= 0) {
                float2 o = make_float2(acc[mt][nt][2] * s2, acc[mt][nt][3] * s2);
                if (res) {
                    float2 rv = *(const float2*)(res + (size_t)t2 * ldc + col);
                    o.x += rv.x; o.y += rv.y;
                }
                *(float2*)(C + (size_t)t2 * ldc + col) = o;
            }
        }
    }
}

// =============== attention scores via HMMA (causal-skip, fp16 1-pass) ===============
#define SC_SMEM (26112*2)

__global__ void __launch_bounds__(256, 2) scores_mma_kernel(
    const __half* __restrict__ qh, const __half* __restrict__ kh,
    float* __restrict__ sc)
{
    extern __shared__ __half smb[];
    int h = blockIdx.z;
    int row0 = blockIdx.y * 64;
    int n0 = blockIdx.x * 128;
    if (n0 >= row0 + 64) return;
    int tid = threadIdx.x, lane = tid & 31, wid = tid >> 5;
    int gr = lane >> 2, tg = lane & 3;
    int wm = wid >> 2, wn = wid & 3;
    uint32_t base = smem_u32(smb);

    {
#pragma unroll
        for (int it = 0; it < 4; it++) {
            int idx = it * 256 + tid;
            int r = idx >> 4, ch = idx & 15;
            cpa16(base + (uint32_t)(r * 136 + ch * 8) * 2,
                  qh + (size_t)(row0 + r) * 2048 + h * 128 + ch * 8);
        }
    }
    {
        uint32_t d0 = base + 8704u * 2;
#pragma unroll
        for (int it = 0; it < 8; it++) {
            int idx = it * 256 + tid;
            int r = idx >> 4, ch = idx & 15;
            cpa16(d0 + (uint32_t)(r * 136 + ch * 8) * 2,
                  kh + (size_t)(n0 + r) * 512 + (h >> 2) * 128 + ch * 8);
        }
    }
    CPA_COMMIT(); CPA_WAIT0();
    __syncthreads();

    float acc[2][4][4];
#pragma unroll
    for (int i = 0; i < 2; i++)
#pragma unroll
        for (int j = 0; j < 4; j++)
#pragma unroll
            for (int r = 0; r < 4; r++) acc[i][j][r] = 0.f;

    int lr = lane & 15, lc8 = (lane & 16) >> 1;
    uint32_t QHb = base;
    uint32_t KHb = base + 17408;

#pragma unroll
    for (int ks = 0; ks < 8; ks++) {
        uint32_t fAH[2][4], fBH[4][2];
#pragma unroll
        for (int mt = 0; mt < 2; mt++) {
            uint32_t ao = (uint32_t)((wm * 32 + mt * 16 + lr) * 136 + ks * 16 + lc8) * 2;
            ldm_x4(fAH[mt], QHb + ao);
        }
#pragma unroll
        for (int half = 0; half < 2; half++) {
            uint32_t bo = (uint32_t)((wn * 32 + half * 16 + lr) * 136 + ks * 16 + lc8) * 2;
            uint32_t rH[4];
            ldm_x4(rH, KHb + bo);
            fBH[half*2][0] = rH[0]; fBH[half*2][1] = rH[2];
            fBH[half*2+1][0] = rH[1]; fBH[half*2+1][1] = rH[3];
        }
#pragma unroll
        for (int mt = 0; mt < 2; mt++)
#pragma unroll
            for (int nt = 0; nt < 4; nt++)
                mma16816(acc[mt][nt], fAH[mt], fBH[nt]);
    }

    const float scale = 0.0883883476483184405f;
    float* out = sc + (size_t)h * Sm * Sm;
#pragma unroll
    for (int mt = 0; mt < 2; mt++) {
        int r1 = row0 + wm * 32 + mt * 16 + gr;
        int r2 = r1 + 8;
#pragma unroll
        for (int nt = 0; nt < 4; nt++) {
            int col = n0 + wn * 32 + nt * 8 + tg * 2;
            *(float2*)(out + (size_t)r1 * Sm + col) =
                make_float2(acc[mt][nt][0] * scale, acc[mt][nt][1] * scale);
            *(float2*)(out + (size_t)r2 * Sm + col) =
                make_float2(acc[mt][nt][2] * scale, acc[mt][nt][3] * scale);
        }
    }
}

// =============== PV via HMMA (causal-truncated, fp16 1-pass) ===============
#define PV_STAGE_B (13312*2)
#define PV_SMEM (2*PV_STAGE_B)

__global__ void __launch_bounds__(256, 2) pv_mma_kernel(
    const __half* __restrict__ ph_, const __half* __restrict__ vh,
    __half* __restrict__ outh)
{
    extern __shared__ __half smb[];
    int h = blockIdx.y;
    int row0 = blockIdx.x * 64;
    int nst = blockIdx.x + 1;
    int kvoff = (h >> 2) * 128;
    int tid = threadIdx.x, lane = tid & 31, wid = tid >> 5;
    int gr = lane >> 2, tg = lane & 3;
    int wm = wid >> 2, wn = wid & 3;
    uint32_t smbase = smem_u32(smb);

    float acc[2][4][4];
#pragma unroll
    for (int i = 0; i < 2; i++)
#pragma unroll
        for (int j = 0; j < 4; j++)
#pragma unroll
            for (int r = 0; r < 4; r++) acc[i][j][r] = 0.f;

    auto copy_stage = [&](int st) {
        uint32_t base = smbase + (uint32_t)(st & 1) * PV_STAGE_B;
        int k0 = st * 64;
#pragma unroll
        for (int it = 0; it < 2; it++) {
            int idx = it * 256 + tid;
            int row = idx >> 3, ch = idx & 7;
            cpa16(base + (uint32_t)(row * 72 + ch * 8) * 2,
                  ph_ + ((size_t)h * Sm + row0 + row) * Sm + k0 + ch * 8);
        }
        {
            uint32_t d0 = base + 4608 * 2;
#pragma unroll
            for (int it = 0; it < 4; it++) {
                int idx = it * 256 + tid;
                int row = idx >> 4, ch = idx & 15;
                cpa16(d0 + (uint32_t)(row * 136 + ch * 8) * 2,
                      vh + (size_t)(k0 + row) * 512 + kvoff + ch * 8);
            }
        }
        CPA_COMMIT();
    };

    copy_stage(0);
    int lr = lane & 15, lc8 = (lane & 16) >> 1;

    for (int st = 0; st < nst; st++) {
        if (st + 1 < nst) { copy_stage(st + 1); CPA_WAIT1(); }
        else              { CPA_WAIT0(); }
        __syncthreads();
        uint32_t base = smbase + (uint32_t)(st & 1) * PV_STAGE_B;
        uint32_t AHb = base;
        uint32_t BHb = base + 9216;
#pragma unroll
        for (int ks = 0; ks < 4; ks++) {
            uint32_t fAH[2][4], fBH[4][2];
#pragma unroll
            for (int mt = 0; mt < 2; mt++) {
                uint32_t ao = (uint32_t)((wm * 32 + mt * 16 + lr) * 72 + ks * 16 + lc8) * 2;
                ldm_x4(fAH[mt], AHb + ao);
            }
#pragma unroll
            for (int half = 0; half < 2; half++) {
                uint32_t bo = (uint32_t)((ks * 16 + lr) * 136 + wn * 32 + half * 16 + lc8) * 2;
                uint32_t rH[4];
                ldm_x4t(rH, BHb + bo);
                fBH[half*2][0] = rH[0]; fBH[half*2][1] = rH[1];
                fBH[half*2+1][0] = rH[2]; fBH[half*2+1][1] = rH[3];
            }
#pragma unroll
            for (int mt = 0; mt < 2; mt++)
#pragma unroll
                for (int nt = 0; nt < 4; nt++)
                    mma16816(acc[mt][nt], fAH[mt], fBH[nt]);
        }
        __syncthreads();
    }

#pragma unroll
    for (int mt = 0; mt < 2; mt++) {
        int r1 = row0 + wm * 32 + mt * 16 + gr;
        int r2 = r1 + 8;
#pragma unroll
        for (int nt = 0; nt < 4; nt++) {
            int col = h * 128 + wn * 32 + nt * 8 + tg * 2;
            __half2 hh1 = __floats2half2_rn(acc[mt][nt][0], acc[mt][nt][1]);
            __half2 hh2 = __floats2half2_rn(acc[mt][nt][2], acc[mt][nt][3]);
            *(__half2*)(outh + (size_t)r1 * 2048 + col) = hh1;
            *(__half2*)(outh + (size_t)r2 * 2048 + col) = hh2;
        }
    }
}

// ---------------- small kernels ----------------
__global__ void rmsnorm_kernel(const float* __restrict__ in, const float* __restrict__ w,
                               float* __restrict__ outf, __half* __restrict__ outh) {
    int t = blockIdx.x;
    const float* row = in + (size_t)t * Dm;
    float s = 0.f;
    for (int d = threadIdx.x; d < Dm; d += 256) { float v = row[d]; s += v * v; }
    __shared__ float red[256];
    red[threadIdx.x] = s; __syncthreads();
    for (int off = 128; off > 0; off >>= 1) {
        if (threadIdx.x < off) red[threadIdx.x] += red[threadIdx.x + off];
        __syncthreads();
    }
    float r = rsqrtf(red[0] / (float)Dm + 1e-5f);
    for (int d = threadIdx.x; d < Dm; d += 256) {
        float v = row[d] * r * w[d];
        if (outf) outf[(size_t)t * Dm + d] = v;
        outh[(size_t)t * Dm + d] = __float2half_rn(v);
    }
}

// log2(500000)/64
#define ROPE_C 0.29580575889569022f

__global__ void rope_planes_kernel(const float* __restrict__ qkv, const int* __restrict__ pos_ids,
                                   __half* qh, __half* kh, __half* vh) {
    int t = blockIdx.x;
    float p = (float)pos_ids[t];
    for (int idx = threadIdx.x; idx < (Hn + HKVn) * 64; idx += blockDim.x) {
        int head = idx >> 6;
        int i = idx & 63;
        float inv = exp2f(-(float)i * ROPE_C);
        float f = p * inv;
        float sn, cs;
        sincosf(f, &sn, &cs);
        if (head < Hn) {
            const float* src = qkv + (size_t)t * QKVP + head * DHn;
            float x1 = src[i], x2 = src[i + 64];
            size_t d = (size_t)t * Dm + head * DHn + i;
            qh[d]      = __float2half_rn(x1 * cs - x2 * sn);
            qh[d + 64] = __float2half_rn(x2 * cs + x1 * sn);
        } else {
            int kvh = head - Hn;
            const float* src = qkv + (size_t)t * QKVP + 2048 + kvh * DHn;
            float x1 = src[i], x2 = src[i + 64];
            size_t d = (size_t)t * 512 + kvh * DHn + i;
            kh[d]      = __float2half_rn(x1 * cs - x2 * sn);
            kh[d + 64] = __float2half_rn(x2 * cs + x1 * sn);
        }
    }
    for (int idx = threadIdx.x; idx < 512; idx += blockDim.x) {
        vh[(size_t)t * 512 + idx] = __float2half_rn(qkv[(size_t)t * QKVP + 2560 + idx]);
    }
}

__global__ void softmax_kernel(const float* __restrict__ sc, const int* __restrict__ mask,
                               __half* __restrict__ ph) {
    int i = blockIdx.x;
    int h = blockIdx.y;
    int row_end = (i & ~63) + 64;
    const float* row = sc + ((size_t)h * Sm + i) * Sm;
    int tid = threadIdx.x;
    int j0 = tid, j1 = tid + 256;
    float s0 = (j0 <= i && mask[j0] > 0) ? row[j0] : -1e9f;
    float s1 = (j1 <= i && mask[j1] > 0) ? row[j1] : -1e9f;
    __shared__ float red[256];
    red[tid] = fmaxf(s0, s1); __syncthreads();
    for (int off = 128; off > 0; off >>= 1) {
        if (tid < off) red[tid] = fmaxf(red[tid], red[tid + off]);
        __syncthreads();
    }
    float m = red[0];
    __syncthreads();
    float e0 = expf(s0 - m), e1 = expf(s1 - m);
    red[tid] = e0 + e1; __syncthreads();
    for (int off = 128; off > 0; off >>= 1) {
        if (tid < off) red[tid] += red[tid + off];
        __syncthreads();
    }
    float inv = 1.f / red[0];
    size_t base = ((size_t)h * Sm + i) * Sm;
    if (j0 < row_end) ph[base + j0] = __float2half_rn(e0 * inv);
    if (j1 < row_end) ph[base + j1] = __float2half_rn(e1 * inv);
}

__global__ void router_kernel(const float* __restrict__ x2, const float* __restrict__ rw,
                              int* __restrict__ topidx, float* __restrict__ topscore) {
    int t = blockIdx.x;
    int w = threadIdx.x >> 5, lane = threadIdx.x & 31;
    float s = 0.f;
    for (int d = lane; d < Dm; d += 32)
        s += x2[(size_t)t * Dm + d] * rw[d * En + w];
    for (int off = 16; off; off >>= 1) s += __shfl_down_sync(0xffffffff, s, off);
    __shared__ float logits[En];
    if (lane == 0) logits[w] = s;
    __syncthreads();
    if (threadIdx.x == 0) {
        int best = 0; float bv = logits[0];
        for (int e = 1; e < En; e++) if (logits[e] > bv) { bv = logits[e]; best = e; }
        topidx[t] = best;
        topscore[t] = 1.f / (1.f + expf(-bv));
    }
}

__global__ void dispatch_kernel(const int* __restrict__ topidx) {
    int t = threadIdx.x;
    if (t < En) g_cnt[t] = 0;
    __syncthreads();
    int e = topidx[t];
    int pos = atomicAdd(&g_cnt[e], 1);
    g_list[e * Sm + pos] = t;
}

// combined silu-mul for expert gu and shared sgu
__global__ void silumul2_kernel(const float* __restrict__ gu, const float* __restrict__ sgu,
                                __half* __restrict__ ah, __half* __restrict__ sh) {
    int i = blockIdx.x * 256 + threadIdx.x;
    const float* src = gu;
    __half* oh = ah;
    int j = i;
    if (i >= Sm * Dm) {
        j = i - Sm * Dm;
        src = sgu; oh = sh;
    }
    int t = j >> 11, c = j & 2047;
    float g = src[(size_t)t * 4096 + c];
    float u = src[(size_t)t * 4096 + 2048 + c];
    float a = (g / (1.f + expf(-g))) * u;
    oh[j] = __float2half_rn(a);
}

__global__ void add3_kernel(const float* __restrict__ a, const float* __restrict__ b,
                            const float* __restrict__ c, float* __restrict__ out) {
    int i = blockIdx.x * 256 + threadIdx.x;
    out[i] = a[i] + b[i] + c[i];
}

// ---------------- launch ----------------
#define GSYM(p, s) cudaGetSymbolAddress((void**)&p, s)
#define NSBIG 0x40000000

extern "C" void kernel_launch(void* const* d_in, const int* in_sizes, int n_in,
                              void* d_out, int out_size) {
    const float* hidden   = (const float*)d_in[0];
    const int*   amask    = (const int*)  d_in[1];
    const int*   pos      = (const int*)  d_in[2];
    const float* attn_nw  = (const float*)d_in[3];
    const float* wq       = (const float*)d_in[4];
    const float* wk       = (const float*)d_in[5];
    const float* wv       = (const float*)d_in[6];
    const float* wo       = (const float*)d_in[7];
    const float* ffn_nw   = (const float*)d_in[8];
    const float* router_w = (const float*)d_in[9];
    const float* w_gate   = (const float*)d_in[10];
    const float* w_up     = (const float*)d_in[11];
    const float* w_down   = (const float*)d_in[12];
    const float* ws_gate  = (const float*)d_in[13];
    const float* ws_up    = (const float*)d_in[14];
    const float* ws_down  = (const float*)d_in[15];
    float* out = (float*)d_out;

    float *pqkv, *psc, *phf, *px2f, *pgu, *psgu, *prouted, *pshared, *pts;
    int *pti;
    __half *pxh, *path, *px2h, *pach, *psah, *pqh, *pkh, *pvh, *pph;
    GSYM(pqkv, g_qkv); GSYM(psc, g_scores); GSYM(phf, g_h); GSYM(px2f, g_x2f);
    GSYM(pgu, g_gu); GSYM(psgu, g_sgu); GSYM(prouted, g_routed); GSYM(pshared, g_shared);
    GSYM(pti, g_topidx); GSYM(pts, g_topscore);
    GSYM(pxh, x_h); GSYM(path, at_h); GSYM(px2h, x2_h); GSYM(pach, ac_h); GSYM(psah, sa_h);
    GSYM(pqh, q_h); GSYM(pkh, k_h); GSYM(pvh, v_h); GSYM(pph, p_h);

    cudaFuncSetAttribute(tgemm_kernel, cudaFuncAttributeMaxDynamicSharedMemorySize, TG_SMEM);
    cudaFuncSetAttribute(scores_mma_kernel, cudaFuncAttributeMaxDynamicSharedMemorySize, SC_SMEM);
    cudaFuncSetAttribute(pv_mma_kernel, cudaFuncAttributeMaxDynamicSharedMemorySize, PV_SMEM);

    // --- attention block ---
    rmsnorm_kernel<<<Sm, 256>>>(hidden, attn_nw, nullptr, pxh);
    tgemm_kernel<<<dim3(24, 4), 256, TG_SMEM>>>(pxh, wq, wk, wv,
                                                2048, 512, 512, 2048, 2560,
                                                pqkv, 3072, nullptr, nullptr, 0,
                                                nullptr, nullptr, nullptr, nullptr);
    rope_planes_kernel<<<Sm, 256>>>(pqkv, pos, pqh, pkh, pvh);
    scores_mma_kernel<<<dim3(4, 8, Hn), 256, SC_SMEM>>>(pqh, pkh, psc);
    softmax_kernel<<<dim3(Sm, Hn), 256>>>(psc, amask, pph);
    pv_mma_kernel<<<dim3(8, Hn), 256, PV_SMEM>>>(pph, pvh, path);
    tgemm_kernel<<<dim3(16, 4), 256, TG_SMEM>>>(path, wo, nullptr, nullptr,
                                                2048, 0, 0, NSBIG, NSBIG,
                                                phf, 2048, hidden, nullptr, 0,
                                                nullptr, nullptr, nullptr, nullptr);

    // --- MoE block ---
    rmsnorm_kernel<<<Sm, 256>>>(phf, ffn_nw, px2f, px2h);
    router_kernel<<<Sm, 256>>>(px2f, router_w, pti, pts);
    dispatch_kernel<<<1, Sm>>>(pti);
    tgemm_kernel<<<dim3(32, 4, En + 1), 256, TG_SMEM>>>(px2h, w_gate, w_up, nullptr,
                                                        2048, 2048, 0, 2048, NSBIG,
                                                        pgu, 4096, nullptr, pts, 1,
                                                        px2h, ws_gate, ws_up, psgu);
    silumul2_kernel<<<(2 * Sm * Dm) / 256, 256>>>(pgu, psgu, pach, psah);
    tgemm_kernel<<<dim3(16, 4, En + 1), 256, TG_SMEM>>>(pach, w_down, nullptr, nullptr,
                                                        2048, 0, 0, NSBIG, NSBIG,
                                                        prouted, 2048, nullptr, nullptr, 1,
                                                        psah, ws_down, nullptr, pshared);

    // final: out = h + routed + shared
    add3_kernel<<<(Sm * Dm) / 256, 256>>>(phf, prouted, pshared, out);
}